// round 4
// baseline (speedup 1.0000x reference)
#include <cuda_runtime.h>
#include <cstdint>

#define NN 50000
#define EE 800000
#define RR 8
#define DIN 64
#define DHID 128
#define DOUT 64
#define NR (NN*RR)
#define LN_EPS 1e-5f

// ---- scratch (device globals; no runtime allocation); 16B-aligned for
// float4 loads/stores and red.global.add.v4.f32 ----
__device__ __align__(16) float g_agg1[(size_t)NN*RR*DIN]; // per-(node,rel) sum of x[src]
__device__ __align__(16) float g_norm[NR];                // 1/cnt per (node,rel), 0 if empty
__device__ __align__(16) int   g_cnt[NR];
__device__ __align__(16) float g_h[(size_t)NN*DHID];      // layer-1 output (post LN)
__device__ __align__(16) float g_hall[(size_t)RR*NN*DOUT];// h @ W2_r for each relation
__device__ __align__(16) float g_oagg[(size_t)NN*DOUT];   // layer-2 normalized message sum

// ------------------------------------------------------------------
// zero the scratch that gets atomically accumulated
__global__ void zero_kernel() {
    size_t i = (size_t)blockIdx.x * blockDim.x + threadIdx.x;
    size_t n_agg1 = (size_t)NN * RR * DIN / 4;   // float4 count
    size_t n_oagg = (size_t)NN * DOUT / 4;
    size_t stride = (size_t)gridDim.x * blockDim.x;
    float4 z = make_float4(0.f, 0.f, 0.f, 0.f);
    for (size_t k = i; k < n_agg1; k += stride)
        reinterpret_cast<float4*>(g_agg1)[k] = z;
    for (size_t k = i; k < n_oagg; k += stride)
        reinterpret_cast<float4*>(g_oagg)[k] = z;
    for (size_t k = i; k < NR; k += stride)
        g_cnt[k] = 0;
}

// ------------------------------------------------------------------
// degree count per (dst, rel)   (indices are int32: JAX x64 disabled)
__global__ void count_kernel(const int* __restrict__ ei,
                             const int* __restrict__ et) {
    int e = blockIdx.x * blockDim.x + threadIdx.x;
    if (e < EE) {
        int d = ei[EE + e];
        int r = et[e];
        atomicAdd(&g_cnt[d * RR + r], 1);
    }
}

__global__ void norm_kernel() {
    int i = blockIdx.x * blockDim.x + threadIdx.x;
    if (i < NR) {
        int c = g_cnt[i];
        g_norm[i] = c > 0 ? 1.0f / (float)c : 0.0f;
    }
}

// ------------------------------------------------------------------
// layer-1 scatter: agg1[dst,rel,:] += x[src,:]   (16 threads / edge, v4 atomics)
__global__ void scatter1_kernel(const float* __restrict__ x,
                                const int* __restrict__ ei,
                                const int* __restrict__ et) {
    unsigned t = blockIdx.x * blockDim.x + threadIdx.x;
    unsigned e = t >> 4;
    unsigned lane = t & 15u;
    if (e >= EE) return;
    int s = ei[e];
    int d = ei[EE + e];
    int r = et[e];
    float4 v = *reinterpret_cast<const float4*>(x + (size_t)s * DIN + lane * 4);
    float* p = g_agg1 + ((size_t)d * RR + r) * DIN + lane * 4;
    asm volatile("red.global.add.v4.f32 [%0], {%1,%2,%3,%4};"
                 :: "l"(p), "f"(v.x), "f"(v.y), "f"(v.z), "f"(v.w) : "memory");
}

// ------------------------------------------------------------------
// layer-1 transform: h = LN(leaky(Ahat @ [W1;root1] + bias1))
// Ahat[n, r*64+d] = agg1[n,r,d]*norm[n,r], Ahat[n, 512+d] = x[n,d]  (K=576)
// BM=64, BN=128, BK=32, 256 threads, 4x8 micro-tile
__global__ __launch_bounds__(256) void transform1_kernel(
    const float* __restrict__ x, const float* __restrict__ W1,
    const float* __restrict__ root1, const float* __restrict__ bias1,
    const float* __restrict__ gamma1, const float* __restrict__ beta1) {
    __shared__ float As[32][65];
    __shared__ float Bs[32][128];
    int m0 = blockIdx.x * 64;
    int tid = threadIdx.x;
    int tx = tid & 15, ty = tid >> 4;
    float acc[4][8];
#pragma unroll
    for (int i = 0; i < 4; i++)
#pragma unroll
        for (int j = 0; j < 8; j++) acc[i][j] = 0.f;

    int am = tid >> 2, ak0 = (tid & 3) * 8;
    int gm_a = m0 + am;
    int bk = tid >> 3, bn0 = (tid & 7) * 16;

    for (int kk = 0; kk < 576; kk += 32) {
#pragma unroll
        for (int i = 0; i < 8; i++) {
            int k = kk + ak0 + i;
            float v = 0.f;
            if (gm_a < NN) {
                if (k < 512) v = g_agg1[(size_t)gm_a * 512 + k] * g_norm[gm_a * 8 + (k >> 6)];
                else         v = x[(size_t)gm_a * 64 + (k - 512)];
            }
            As[ak0 + i][am] = v;
        }
        {
            int k = kk + bk;
            const float* Brow = (k < 512) ? (W1 + (size_t)k * 128)
                                          : (root1 + (size_t)(k - 512) * 128);
#pragma unroll
            for (int i = 0; i < 16; i += 4)
                *reinterpret_cast<float4*>(&Bs[bk][bn0 + i]) =
                    *reinterpret_cast<const float4*>(Brow + bn0 + i);
        }
        __syncthreads();
#pragma unroll
        for (int k = 0; k < 32; k++) {
            float a[4], b[8];
#pragma unroll
            for (int i = 0; i < 4; i++) a[i] = As[k][ty * 4 + i];
#pragma unroll
            for (int j = 0; j < 8; j++) b[j] = Bs[k][tx * 8 + j];
#pragma unroll
            for (int i = 0; i < 4; i++)
#pragma unroll
                for (int j = 0; j < 8; j++) acc[i][j] = fmaf(a[i], b[j], acc[i][j]);
        }
        __syncthreads();
    }
    // epilogue: bias + LeakyReLU(0.2) + LayerNorm over 128 cols
    float gam[8], bet[8], bia[8];
#pragma unroll
    for (int j = 0; j < 8; j++) {
        int c = tx * 8 + j;
        bia[j] = bias1[c]; gam[j] = gamma1[c]; bet[j] = beta1[c];
    }
#pragma unroll
    for (int i = 0; i < 4; i++) {
        int gm = m0 + ty * 4 + i;
        float v[8]; float s = 0.f, s2 = 0.f;
#pragma unroll
        for (int j = 0; j < 8; j++) {
            float u = acc[i][j] + bia[j];
            u = (u >= 0.f) ? u : 0.2f * u;
            v[j] = u; s += u; s2 += u * u;
        }
        // 128 cols live on 16 contiguous lanes (same ty) -> width-16 shuffle reduce
#pragma unroll
        for (int off = 8; off; off >>= 1) {
            s  += __shfl_xor_sync(0xffffffffu, s, off);
            s2 += __shfl_xor_sync(0xffffffffu, s2, off);
        }
        float mu = s * (1.f / 128.f);
        float var = s2 * (1.f / 128.f) - mu * mu;
        float rstd = rsqrtf(var + LN_EPS);
        if (gm < NN) {
            float o[8];
#pragma unroll
            for (int j = 0; j < 8; j++) o[j] = (v[j] - mu) * rstd * gam[j] + bet[j];
            *reinterpret_cast<float4*>(&g_h[(size_t)gm * 128 + tx * 8]) =
                make_float4(o[0], o[1], o[2], o[3]);
            *reinterpret_cast<float4*>(&g_h[(size_t)gm * 128 + tx * 8 + 4]) =
                make_float4(o[4], o[5], o[6], o[7]);
        }
    }
}

// ------------------------------------------------------------------
// layer-2 per-relation transform: h_all[r] = h @ W2_r   (M=N,K=128,N=64)
// BM=64, BN=64, BK=32, 256 threads, 4x4 micro-tile; grid.y = relation
__global__ __launch_bounds__(256) void transform2_kernel(const float* __restrict__ W2) {
    __shared__ float As[32][65];
    __shared__ float Bs[32][64];
    int m0 = blockIdx.x * 64;
    int r = blockIdx.y;
    const float* Wr = W2 + (size_t)r * 128 * 64;
    int tid = threadIdx.x;
    int tx = tid & 15, ty = tid >> 4;
    float acc[4][4];
#pragma unroll
    for (int i = 0; i < 4; i++)
#pragma unroll
        for (int j = 0; j < 4; j++) acc[i][j] = 0.f;

    int am = tid >> 2, ak0 = (tid & 3) * 8;
    int gm_a = m0 + am;
    int bk = tid >> 3, bn0 = (tid & 7) * 8;

    for (int kk = 0; kk < 128; kk += 32) {
#pragma unroll
        for (int i = 0; i < 8; i++) {
            float v = (gm_a < NN) ? g_h[(size_t)gm_a * 128 + kk + ak0 + i] : 0.f;
            As[ak0 + i][am] = v;
        }
#pragma unroll
        for (int i = 0; i < 8; i += 4)
            *reinterpret_cast<float4*>(&Bs[bk][bn0 + i]) =
                *reinterpret_cast<const float4*>(Wr + (size_t)(kk + bk) * 64 + bn0 + i);
        __syncthreads();
#pragma unroll
        for (int k = 0; k < 32; k++) {
            float a[4], b[4];
#pragma unroll
            for (int i = 0; i < 4; i++) a[i] = As[k][ty * 4 + i];
#pragma unroll
            for (int j = 0; j < 4; j++) b[j] = Bs[k][tx * 4 + j];
#pragma unroll
            for (int i = 0; i < 4; i++)
#pragma unroll
                for (int j = 0; j < 4; j++) acc[i][j] = fmaf(a[i], b[j], acc[i][j]);
        }
        __syncthreads();
    }
#pragma unroll
    for (int i = 0; i < 4; i++) {
        int gm = m0 + ty * 4 + i;
        if (gm < NN)
            *reinterpret_cast<float4*>(&g_hall[((size_t)r * NN + gm) * 64 + tx * 4]) =
                make_float4(acc[i][0], acc[i][1], acc[i][2], acc[i][3]);
    }
}

// ------------------------------------------------------------------
// layer-2 scatter: oagg[dst,:] += norm * h_all[rel, src, :]
__global__ void scatter2_kernel(const int* __restrict__ ei,
                                const int* __restrict__ et) {
    unsigned t = blockIdx.x * blockDim.x + threadIdx.x;
    unsigned e = t >> 4;
    unsigned lane = t & 15u;
    if (e >= EE) return;
    int s = ei[e];
    int d = ei[EE + e];
    int r = et[e];
    float nrm = g_norm[d * RR + r];
    float4 v = *reinterpret_cast<const float4*>(g_hall + ((size_t)r * NN + s) * 64 + lane * 4);
    v.x *= nrm; v.y *= nrm; v.z *= nrm; v.w *= nrm;
    float* p = g_oagg + (size_t)d * 64 + lane * 4;
    asm volatile("red.global.add.v4.f32 [%0], {%1,%2,%3,%4};"
                 :: "l"(p), "f"(v.x), "f"(v.y), "f"(v.z), "f"(v.w) : "memory");
}

// ------------------------------------------------------------------
// final: out = LN(oagg + h @ root2 + bias2)   (M=N,K=128,N=64)
__global__ __launch_bounds__(256) void final_kernel(
    const float* __restrict__ root2, const float* __restrict__ bias2,
    const float* __restrict__ gamma2, const float* __restrict__ beta2,
    float* __restrict__ out) {
    __shared__ float As[32][65];
    __shared__ float Bs[32][64];
    int m0 = blockIdx.x * 64;
    int tid = threadIdx.x;
    int tx = tid & 15, ty = tid >> 4;
    float acc[4][4];
#pragma unroll
    for (int i = 0; i < 4; i++)
#pragma unroll
        for (int j = 0; j < 4; j++) acc[i][j] = 0.f;

    int am = tid >> 2, ak0 = (tid & 3) * 8;
    int gm_a = m0 + am;
    int bk = tid >> 3, bn0 = (tid & 7) * 8;

    for (int kk = 0; kk < 128; kk += 32) {
#pragma unroll
        for (int i = 0; i < 8; i++) {
            float v = (gm_a < NN) ? g_h[(size_t)gm_a * 128 + kk + ak0 + i] : 0.f;
            As[ak0 + i][am] = v;
        }
#pragma unroll
        for (int i = 0; i < 8; i += 4)
            *reinterpret_cast<float4*>(&Bs[bk][bn0 + i]) =
                *reinterpret_cast<const float4*>(root2 + (size_t)(kk + bk) * 64 + bn0 + i);
        __syncthreads();
#pragma unroll
        for (int k = 0; k < 32; k++) {
            float a[4], b[4];
#pragma unroll
            for (int i = 0; i < 4; i++) a[i] = As[k][ty * 4 + i];
#pragma unroll
            for (int j = 0; j < 4; j++) b[j] = Bs[k][tx * 4 + j];
#pragma unroll
            for (int i = 0; i < 4; i++)
#pragma unroll
                for (int j = 0; j < 4; j++) acc[i][j] = fmaf(a[i], b[j], acc[i][j]);
        }
        __syncthreads();
    }
    float gam[4], bet[4], bia[4];
#pragma unroll
    for (int j = 0; j < 4; j++) {
        int c = tx * 4 + j;
        bia[j] = bias2[c]; gam[j] = gamma2[c]; bet[j] = beta2[c];
    }
#pragma unroll
    for (int i = 0; i < 4; i++) {
        int gm = m0 + ty * 4 + i;
        float v[4]; float s = 0.f, s2 = 0.f;
#pragma unroll
        for (int j = 0; j < 4; j++) {
            float og = (gm < NN) ? g_oagg[(size_t)gm * 64 + tx * 4 + j] : 0.f;
            float u = acc[i][j] + og + bia[j];
            v[j] = u; s += u; s2 += u * u;
        }
#pragma unroll
        for (int off = 8; off; off >>= 1) {
            s  += __shfl_xor_sync(0xffffffffu, s, off);
            s2 += __shfl_xor_sync(0xffffffffu, s2, off);
        }
        float mu = s * (1.f / 64.f);
        float var = s2 * (1.f / 64.f) - mu * mu;
        float rstd = rsqrtf(var + LN_EPS);
        if (gm < NN) {
            float o[4];
#pragma unroll
            for (int j = 0; j < 4; j++) o[j] = (v[j] - mu) * rstd * gam[j] + bet[j];
            *reinterpret_cast<float4*>(&out[(size_t)gm * 64 + tx * 4]) =
                make_float4(o[0], o[1], o[2], o[3]);
        }
    }
}

// ------------------------------------------------------------------
extern "C" void kernel_launch(void* const* d_in, const int* in_sizes, int n_in,
                              void* d_out, int out_size) {
    const float* x      = (const float*)d_in[0];
    const int*   ei     = (const int*)d_in[1];  // [2,E] int32: src row then dst row
    const int*   et     = (const int*)d_in[2];  // [E] int32
    const float* W1     = (const float*)d_in[3];
    const float* root1  = (const float*)d_in[4];
    const float* bias1  = (const float*)d_in[5];
    const float* gamma1 = (const float*)d_in[6];
    const float* beta1  = (const float*)d_in[7];
    const float* W2     = (const float*)d_in[8];
    const float* root2  = (const float*)d_in[9];
    const float* bias2  = (const float*)d_in[10];
    const float* gamma2 = (const float*)d_in[11];
    const float* beta2  = (const float*)d_in[12];
    float*       out    = (float*)d_out;

    zero_kernel<<<1024, 256>>>();
    count_kernel<<<(EE + 255) / 256, 256>>>(ei, et);
    scatter1_kernel<<<(EE * 16 + 255) / 256, 256>>>(x, ei, et);
    norm_kernel<<<(NR + 255) / 256, 256>>>();
    transform1_kernel<<<(NN + 63) / 64, 256>>>(x, W1, root1, bias1, gamma1, beta1);
    dim3 g2((NN + 63) / 64, RR);
    transform2_kernel<<<g2, 256>>>(W2);
    scatter2_kernel<<<(EE * 16 + 255) / 256, 256>>>(ei, et);
    final_kernel<<<(NN + 63) / 64, 256>>>(root2, bias2, gamma2, beta2, out);
}

// round 5
// speedup vs baseline: 2.0802x; 2.0802x over previous
#include <cuda_runtime.h>
#include <cstdint>

#define NN 50000
#define EE 800000
#define RR 8
#define DIN 64
#define DHID 128
#define DOUT 64
#define NR (NN*RR)
#define LN_EPS 1e-5f

// ---- scratch (device globals; no runtime allocation); 16B-aligned ----
__device__ __align__(16) float g_agg1[(size_t)NN*RR*DIN]; // per-(node,rel) sum of x[src]
__device__ __align__(16) float g_norm[NR];                // 1/cnt per (node,rel)
__device__ __align__(16) int   g_cnt[NR];
__device__ __align__(16) float g_h[(size_t)NN*DHID];      // layer-1 output (post LN)
__device__ __align__(16) float g_hall[(size_t)RR*NN*DOUT];// h @ W2_r per relation
__device__ __align__(16) float g_oagg[(size_t)NN*DOUT];   // layer-2 normalized msg sum

__device__ __forceinline__ uint32_t f2tf32(float f) {
    uint32_t v;
    asm("cvt.rna.tf32.f32 %0, %1;" : "=r"(v) : "f"(f));
    return v;
}

__device__ __forceinline__ void mma_tf32(float* c, uint32_t a0, uint32_t a1,
                                         uint32_t a2, uint32_t a3,
                                         uint32_t b0, uint32_t b1) {
    asm volatile(
        "mma.sync.aligned.m16n8k8.row.col.f32.tf32.tf32.f32 "
        "{%0,%1,%2,%3}, {%4,%5,%6,%7}, {%8,%9}, {%0,%1,%2,%3};"
        : "+f"(c[0]), "+f"(c[1]), "+f"(c[2]), "+f"(c[3])
        : "r"(a0), "r"(a1), "r"(a2), "r"(a3), "r"(b0), "r"(b1));
}

// ------------------------------------------------------------------
__global__ void zero_kernel() {
    size_t i = (size_t)blockIdx.x * blockDim.x + threadIdx.x;
    size_t n_agg1 = (size_t)NN * RR * DIN / 4;
    size_t n_oagg = (size_t)NN * DOUT / 4;
    size_t stride = (size_t)gridDim.x * blockDim.x;
    float4 z = make_float4(0.f, 0.f, 0.f, 0.f);
    for (size_t k = i; k < n_agg1; k += stride)
        reinterpret_cast<float4*>(g_agg1)[k] = z;
    for (size_t k = i; k < n_oagg; k += stride)
        reinterpret_cast<float4*>(g_oagg)[k] = z;
    for (size_t k = i; k < NR; k += stride)
        g_cnt[k] = 0;
}

__global__ void count_kernel(const int* __restrict__ ei,
                             const int* __restrict__ et) {
    int e = blockIdx.x * blockDim.x + threadIdx.x;
    if (e < EE) atomicAdd(&g_cnt[ei[EE + e] * RR + et[e]], 1);
}

__global__ void norm_kernel() {
    int i = blockIdx.x * blockDim.x + threadIdx.x;
    if (i < NR) {
        int c = g_cnt[i];
        g_norm[i] = c > 0 ? 1.0f / (float)c : 0.0f;
    }
}

// layer-1 scatter: agg1[dst,rel,:] += x[src,:]
__global__ void scatter1_kernel(const float* __restrict__ x,
                                const int* __restrict__ ei,
                                const int* __restrict__ et) {
    unsigned t = blockIdx.x * blockDim.x + threadIdx.x;
    unsigned e = t >> 4;
    unsigned lane = t & 15u;
    if (e >= EE) return;
    int s = ei[e];
    int d = ei[EE + e];
    int r = et[e];
    float4 v = *reinterpret_cast<const float4*>(x + (size_t)s * DIN + lane * 4);
    float* p = g_agg1 + ((size_t)d * RR + r) * DIN + lane * 4;
    asm volatile("red.global.add.v4.f32 [%0], {%1,%2,%3,%4};"
                 :: "l"(p), "f"(v.x), "f"(v.y), "f"(v.z), "f"(v.w) : "memory");
}

// ------------------------------------------------------------------
// layer-1 transform (tensor-core tf32): h = LN(leaky(Ahat @ [W1;root1] + bias1))
// Ahat[n, r*64+d] = agg1[n,r,d]*norm[n,r]; Ahat[n, 512+d] = x[n,d]; K=576
// BM=128 (8 warps x m16), BN=128 (16 n-tiles), BK=32.
__global__ __launch_bounds__(256) void transform1_tc(
    const float* __restrict__ x, const float* __restrict__ W1,
    const float* __restrict__ root1, const float* __restrict__ bias1,
    const float* __restrict__ gamma1, const float* __restrict__ beta1) {
    __shared__ uint32_t As[128][36];   // stride 36: bank = 4*qr + qc (conflict-free frag reads)
    __shared__ uint32_t Bs[32][136];   // stride 136: bank = 8*qc + qr (conflict-free)
    int tid = threadIdx.x;
    int m0 = blockIdx.x * 128;
    int lane = tid & 31, warp = tid >> 5;
    int qr = lane >> 2, qc = lane & 3;

    float acc[16][4];
#pragma unroll
    for (int t = 0; t < 16; t++)
#pragma unroll
        for (int j = 0; j < 4; j++) acc[t][j] = 0.f;

    int arow = tid >> 1, akoff = (tid & 1) * 16;       // A: 1 row, 16 k per thread
    int brow = tid >> 3, bcoff = (tid & 7) * 16;       // B: 1 k-row, 16 cols per thread

    for (int kk = 0; kk < 576; kk += 32) {
        // ---- A slab: rows m0..m0+127, k in [kk, kk+32) ----
        {
            int n = m0 + arow;
            int kg = kk + akoff;
            float va[16];
            if (n < NN) {
                if (kg < 512) {
                    float nrm = g_norm[n * 8 + (kg >> 6)];
                    const float4* src =
                        reinterpret_cast<const float4*>(g_agg1 + (size_t)n * 512 + kg);
#pragma unroll
                    for (int i = 0; i < 4; i++) {
                        float4 v = src[i];
                        va[4*i+0] = v.x * nrm; va[4*i+1] = v.y * nrm;
                        va[4*i+2] = v.z * nrm; va[4*i+3] = v.w * nrm;
                    }
                } else {
                    const float4* src =
                        reinterpret_cast<const float4*>(x + (size_t)n * 64 + (kg - 512));
#pragma unroll
                    for (int i = 0; i < 4; i++) {
                        float4 v = src[i];
                        va[4*i+0] = v.x; va[4*i+1] = v.y;
                        va[4*i+2] = v.z; va[4*i+3] = v.w;
                    }
                }
            } else {
#pragma unroll
                for (int i = 0; i < 16; i++) va[i] = 0.f;
            }
#pragma unroll
            for (int i = 0; i < 16; i++) As[arow][akoff + i] = f2tf32(va[i]);
        }
        // ---- B slab: k-row kk+brow, all 128 cols ----
        {
            int kg = kk + brow;
            const float* Brow = (kg < 512) ? (W1 + (size_t)kg * 128)
                                           : (root1 + (size_t)(kg - 512) * 128);
            const float4* src = reinterpret_cast<const float4*>(Brow + bcoff);
#pragma unroll
            for (int i = 0; i < 4; i++) {
                float4 v = src[i];
                Bs[brow][bcoff + 4*i + 0] = f2tf32(v.x);
                Bs[brow][bcoff + 4*i + 1] = f2tf32(v.y);
                Bs[brow][bcoff + 4*i + 2] = f2tf32(v.z);
                Bs[brow][bcoff + 4*i + 3] = f2tf32(v.w);
            }
        }
        __syncthreads();
#pragma unroll
        for (int k8 = 0; k8 < 4; k8++) {
            int k0 = k8 * 8;
            int ar = warp * 16 + qr;
            uint32_t a0 = As[ar][k0 + qc];
            uint32_t a1 = As[ar + 8][k0 + qc];
            uint32_t a2 = As[ar][k0 + qc + 4];
            uint32_t a3 = As[ar + 8][k0 + qc + 4];
#pragma unroll
            for (int t = 0; t < 16; t++) {
                uint32_t b0 = Bs[k0 + qc][t * 8 + qr];
                uint32_t b1 = Bs[k0 + qc + 4][t * 8 + qr];
                mma_tf32(acc[t], a0, a1, a2, a3, b0, b1);
            }
        }
        __syncthreads();
    }

    // ---- epilogue: bias + LeakyReLU + LN(128) ----
    // thread owns rows r1 = warp*16+qr, r2 = r1+8; cols t*8 + 2qc, +1
    int r1 = m0 + warp * 16 + qr;
    int r2 = r1 + 8;
    float s1 = 0.f, q1 = 0.f, s2 = 0.f, q2 = 0.f;
#pragma unroll
    for (int t = 0; t < 16; t++) {
        int c = t * 8 + 2 * qc;
        float b0v = bias1[c], b1v = bias1[c + 1];
        float u;
        u = acc[t][0] + b0v; u = u >= 0.f ? u : 0.2f * u; acc[t][0] = u; s1 += u; q1 += u * u;
        u = acc[t][1] + b1v; u = u >= 0.f ? u : 0.2f * u; acc[t][1] = u; s1 += u; q1 += u * u;
        u = acc[t][2] + b0v; u = u >= 0.f ? u : 0.2f * u; acc[t][2] = u; s2 += u; q2 += u * u;
        u = acc[t][3] + b1v; u = u >= 0.f ? u : 0.2f * u; acc[t][3] = u; s2 += u; q2 += u * u;
    }
#pragma unroll
    for (int off = 1; off <= 2; off <<= 1) {
        s1 += __shfl_xor_sync(0xffffffffu, s1, off);
        q1 += __shfl_xor_sync(0xffffffffu, q1, off);
        s2 += __shfl_xor_sync(0xffffffffu, s2, off);
        q2 += __shfl_xor_sync(0xffffffffu, q2, off);
    }
    float mu1 = s1 * (1.f / 128.f), mu2 = s2 * (1.f / 128.f);
    float rs1 = rsqrtf(q1 * (1.f / 128.f) - mu1 * mu1 + LN_EPS);
    float rs2 = rsqrtf(q2 * (1.f / 128.f) - mu2 * mu2 + LN_EPS);
#pragma unroll
    for (int t = 0; t < 16; t++) {
        int c = t * 8 + 2 * qc;
        float g0 = gamma1[c], g1 = gamma1[c + 1];
        float e0 = beta1[c], e1 = beta1[c + 1];
        if (r1 < NN) {
            float2 o = make_float2((acc[t][0] - mu1) * rs1 * g0 + e0,
                                   (acc[t][1] - mu1) * rs1 * g1 + e1);
            *reinterpret_cast<float2*>(&g_h[(size_t)r1 * 128 + c]) = o;
        }
        if (r2 < NN) {
            float2 o = make_float2((acc[t][2] - mu2) * rs2 * g0 + e0,
                                   (acc[t][3] - mu2) * rs2 * g1 + e1);
            *reinterpret_cast<float2*>(&g_h[(size_t)r2 * 128 + c]) = o;
        }
    }
}

// ------------------------------------------------------------------
// layer-2 per-relation transform (tf32): h_all[r] = h @ W2_r   (K=128, N=64)
__global__ __launch_bounds__(256) void transform2_tc(const float* __restrict__ W2) {
    __shared__ uint32_t As[128][36];
    __shared__ uint32_t Bs[32][72];    // stride 72 ≡ 8 mod 32: conflict-free
    int tid = threadIdx.x;
    int m0 = blockIdx.x * 128;
    int r = blockIdx.y;
    const float* Wr = W2 + (size_t)r * 128 * 64;
    int lane = tid & 31, warp = tid >> 5;
    int qr = lane >> 2, qc = lane & 3;

    float acc[8][4];
#pragma unroll
    for (int t = 0; t < 8; t++)
#pragma unroll
        for (int j = 0; j < 4; j++) acc[t][j] = 0.f;

    int arow = tid >> 1, akoff = (tid & 1) * 16;
    int brow = tid >> 3, bcoff = (tid & 7) * 8;   // 32x64: 8 cols per thread

    for (int kk = 0; kk < 128; kk += 32) {
        {
            int n = m0 + arow;
            if (n < NN) {
                const float4* src =
                    reinterpret_cast<const float4*>(g_h + (size_t)n * 128 + kk + akoff);
#pragma unroll
                for (int i = 0; i < 4; i++) {
                    float4 v = src[i];
                    As[arow][akoff + 4*i + 0] = f2tf32(v.x);
                    As[arow][akoff + 4*i + 1] = f2tf32(v.y);
                    As[arow][akoff + 4*i + 2] = f2tf32(v.z);
                    As[arow][akoff + 4*i + 3] = f2tf32(v.w);
                }
            } else {
#pragma unroll
                for (int i = 0; i < 16; i++) As[arow][akoff + i] = 0u;
            }
        }
        {
            const float4* src =
                reinterpret_cast<const float4*>(Wr + (size_t)(kk + brow) * 64 + bcoff);
#pragma unroll
            for (int i = 0; i < 2; i++) {
                float4 v = src[i];
                Bs[brow][bcoff + 4*i + 0] = f2tf32(v.x);
                Bs[brow][bcoff + 4*i + 1] = f2tf32(v.y);
                Bs[brow][bcoff + 4*i + 2] = f2tf32(v.z);
                Bs[brow][bcoff + 4*i + 3] = f2tf32(v.w);
            }
        }
        __syncthreads();
#pragma unroll
        for (int k8 = 0; k8 < 4; k8++) {
            int k0 = k8 * 8;
            int ar = warp * 16 + qr;
            uint32_t a0 = As[ar][k0 + qc];
            uint32_t a1 = As[ar + 8][k0 + qc];
            uint32_t a2 = As[ar][k0 + qc + 4];
            uint32_t a3 = As[ar + 8][k0 + qc + 4];
#pragma unroll
            for (int t = 0; t < 8; t++) {
                uint32_t b0 = Bs[k0 + qc][t * 8 + qr];
                uint32_t b1 = Bs[k0 + qc + 4][t * 8 + qr];
                mma_tf32(acc[t], a0, a1, a2, a3, b0, b1);
            }
        }
        __syncthreads();
    }
    int r1 = m0 + warp * 16 + qr;
    int r2 = r1 + 8;
#pragma unroll
    for (int t = 0; t < 8; t++) {
        int c = t * 8 + 2 * qc;
        if (r1 < NN)
            *reinterpret_cast<float2*>(&g_hall[((size_t)r * NN + r1) * 64 + c]) =
                make_float2(acc[t][0], acc[t][1]);
        if (r2 < NN)
            *reinterpret_cast<float2*>(&g_hall[((size_t)r * NN + r2) * 64 + c]) =
                make_float2(acc[t][2], acc[t][3]);
    }
}

// ------------------------------------------------------------------
// layer-2 scatter: oagg[dst,:] += norm * h_all[rel, src, :]
__global__ void scatter2_kernel(const int* __restrict__ ei,
                                const int* __restrict__ et) {
    unsigned t = blockIdx.x * blockDim.x + threadIdx.x;
    unsigned e = t >> 4;
    unsigned lane = t & 15u;
    if (e >= EE) return;
    int s = ei[e];
    int d = ei[EE + e];
    int r = et[e];
    float nrm = g_norm[d * RR + r];
    float4 v = *reinterpret_cast<const float4*>(g_hall + ((size_t)r * NN + s) * 64 + lane * 4);
    v.x *= nrm; v.y *= nrm; v.z *= nrm; v.w *= nrm;
    float* p = g_oagg + (size_t)d * 64 + lane * 4;
    asm volatile("red.global.add.v4.f32 [%0], {%1,%2,%3,%4};"
                 :: "l"(p), "f"(v.x), "f"(v.y), "f"(v.z), "f"(v.w) : "memory");
}

// ------------------------------------------------------------------
// final (tf32): out = LN(oagg + h @ root2 + bias2)   (K=128, N=64)
__global__ __launch_bounds__(256) void final_tc(
    const float* __restrict__ root2, const float* __restrict__ bias2,
    const float* __restrict__ gamma2, const float* __restrict__ beta2,
    float* __restrict__ out) {
    __shared__ uint32_t As[128][36];
    __shared__ uint32_t Bs[32][72];
    int tid = threadIdx.x;
    int m0 = blockIdx.x * 128;
    int lane = tid & 31, warp = tid >> 5;
    int qr = lane >> 2, qc = lane & 3;

    float acc[8][4];
#pragma unroll
    for (int t = 0; t < 8; t++)
#pragma unroll
        for (int j = 0; j < 4; j++) acc[t][j] = 0.f;

    int arow = tid >> 1, akoff = (tid & 1) * 16;
    int brow = tid >> 3, bcoff = (tid & 7) * 8;

    for (int kk = 0; kk < 128; kk += 32) {
        {
            int n = m0 + arow;
            if (n < NN) {
                const float4* src =
                    reinterpret_cast<const float4*>(g_h + (size_t)n * 128 + kk + akoff);
#pragma unroll
                for (int i = 0; i < 4; i++) {
                    float4 v = src[i];
                    As[arow][akoff + 4*i + 0] = f2tf32(v.x);
                    As[arow][akoff + 4*i + 1] = f2tf32(v.y);
                    As[arow][akoff + 4*i + 2] = f2tf32(v.z);
                    As[arow][akoff + 4*i + 3] = f2tf32(v.w);
                }
            } else {
#pragma unroll
                for (int i = 0; i < 16; i++) As[arow][akoff + i] = 0u;
            }
        }
        {
            const float4* src =
                reinterpret_cast<const float4*>(root2 + (size_t)(kk + brow) * 64 + bcoff);
#pragma unroll
            for (int i = 0; i < 2; i++) {
                float4 v = src[i];
                Bs[brow][bcoff + 4*i + 0] = f2tf32(v.x);
                Bs[brow][bcoff + 4*i + 1] = f2tf32(v.y);
                Bs[brow][bcoff + 4*i + 2] = f2tf32(v.z);
                Bs[brow][bcoff + 4*i + 3] = f2tf32(v.w);
            }
        }
        __syncthreads();
#pragma unroll
        for (int k8 = 0; k8 < 4; k8++) {
            int k0 = k8 * 8;
            int ar = warp * 16 + qr;
            uint32_t a0 = As[ar][k0 + qc];
            uint32_t a1 = As[ar + 8][k0 + qc];
            uint32_t a2 = As[ar][k0 + qc + 4];
            uint32_t a3 = As[ar + 8][k0 + qc + 4];
#pragma unroll
            for (int t = 0; t < 8; t++) {
                uint32_t b0 = Bs[k0 + qc][t * 8 + qr];
                uint32_t b1 = Bs[k0 + qc + 4][t * 8 + qr];
                mma_tf32(acc[t], a0, a1, a2, a3, b0, b1);
            }
        }
        __syncthreads();
    }

    // epilogue: + oagg + bias2, LN(64)
    int r1 = m0 + warp * 16 + qr;
    int r2 = r1 + 8;
    float s1 = 0.f, q1 = 0.f, s2 = 0.f, q2 = 0.f;
#pragma unroll
    for (int t = 0; t < 8; t++) {
        int c = t * 8 + 2 * qc;
        float b0v = bias2[c], b1v = bias2[c + 1];
        float2 o1 = (r1 < NN)
            ? *reinterpret_cast<const float2*>(&g_oagg[(size_t)r1 * 64 + c])
            : make_float2(0.f, 0.f);
        float2 o2 = (r2 < NN)
            ? *reinterpret_cast<const float2*>(&g_oagg[(size_t)r2 * 64 + c])
            : make_float2(0.f, 0.f);
        float u;
        u = acc[t][0] + o1.x + b0v; acc[t][0] = u; s1 += u; q1 += u * u;
        u = acc[t][1] + o1.y + b1v; acc[t][1] = u; s1 += u; q1 += u * u;
        u = acc[t][2] + o2.x + b0v; acc[t][2] = u; s2 += u; q2 += u * u;
        u = acc[t][3] + o2.y + b1v; acc[t][3] = u; s2 += u; q2 += u * u;
    }
#pragma unroll
    for (int off = 1; off <= 2; off <<= 1) {
        s1 += __shfl_xor_sync(0xffffffffu, s1, off);
        q1 += __shfl_xor_sync(0xffffffffu, q1, off);
        s2 += __shfl_xor_sync(0xffffffffu, s2, off);
        q2 += __shfl_xor_sync(0xffffffffu, q2, off);
    }
    float mu1 = s1 * (1.f / 64.f), mu2 = s2 * (1.f / 64.f);
    float rs1 = rsqrtf(q1 * (1.f / 64.f) - mu1 * mu1 + LN_EPS);
    float rs2 = rsqrtf(q2 * (1.f / 64.f) - mu2 * mu2 + LN_EPS);
#pragma unroll
    for (int t = 0; t < 8; t++) {
        int c = t * 8 + 2 * qc;
        float g0 = gamma2[c], g1 = gamma2[c + 1];
        float e0 = beta2[c], e1 = beta2[c + 1];
        if (r1 < NN)
            *reinterpret_cast<float2*>(&out[(size_t)r1 * 64 + c]) =
                make_float2((acc[t][0] - mu1) * rs1 * g0 + e0,
                            (acc[t][1] - mu1) * rs1 * g1 + e1);
        if (r2 < NN)
            *reinterpret_cast<float2*>(&out[(size_t)r2 * 64 + c]) =
                make_float2((acc[t][2] - mu2) * rs2 * g0 + e0,
                            (acc[t][3] - mu2) * rs2 * g1 + e1);
    }
}

// ------------------------------------------------------------------
extern "C" void kernel_launch(void* const* d_in, const int* in_sizes, int n_in,
                              void* d_out, int out_size) {
    const float* x      = (const float*)d_in[0];
    const int*   ei     = (const int*)d_in[1];  // [2,E] int32: src row, dst row
    const int*   et     = (const int*)d_in[2];  // [E] int32
    const float* W1     = (const float*)d_in[3];
    const float* root1  = (const float*)d_in[4];
    const float* bias1  = (const float*)d_in[5];
    const float* gamma1 = (const float*)d_in[6];
    const float* beta1  = (const float*)d_in[7];
    const float* W2     = (const float*)d_in[8];
    const float* root2  = (const float*)d_in[9];
    const float* bias2  = (const float*)d_in[10];
    const float* gamma2 = (const float*)d_in[11];
    const float* beta2  = (const float*)d_in[12];
    float*       out    = (float*)d_out;

    zero_kernel<<<1024, 256>>>();
    count_kernel<<<(EE + 255) / 256, 256>>>(ei, et);
    scatter1_kernel<<<(EE * 16 + 255) / 256, 256>>>(x, ei, et);
    norm_kernel<<<(NR + 255) / 256, 256>>>();
    int mblocks = (NN + 127) / 128;
    transform1_tc<<<mblocks, 256>>>(x, W1, root1, bias1, gamma1, beta1);
    dim3 g2(mblocks, RR);
    transform2_tc<<<g2, 256>>>(W2);
    scatter2_kernel<<<(EE * 16 + 255) / 256, 256>>>(ei, et);
    final_tc<<<mblocks, 256>>>(root2, bias2, gamma2, beta2, out);
}

// round 6
// speedup vs baseline: 2.3209x; 1.1157x over previous
#include <cuda_runtime.h>
#include <cstdint>

#define NN 50000
#define EE 800000
#define RR 8
#define DIN 64
#define DHID 128
#define DOUT 64
#define NR (NN*RR)
#define LN_EPS 1e-5f

// ---- scratch (device globals; no runtime allocation); 16B-aligned ----
__device__ __align__(16) float g_agg1[(size_t)NN*RR*DIN]; // per-(node,rel) sum of x[src]
__device__ __align__(16) float g_norm[NR];                // 1/cnt per (node,rel)
__device__ __align__(16) int   g_cnt[NR];
__device__ __align__(16) float g_h[(size_t)NN*DHID];      // layer-1 output (post LN)
__device__ __align__(16) float g_hall[(size_t)RR*NN*DOUT];// h @ W2_r per relation
__device__ __align__(16) float g_oagg[(size_t)NN*DOUT];   // h@root2 + normalized msg sum

__device__ __forceinline__ uint32_t f2tf32(float f) {
    uint32_t v;
    asm("cvt.rna.tf32.f32 %0, %1;" : "=r"(v) : "f"(f));
    return v;
}

__device__ __forceinline__ void mma_tf32(float* c, uint32_t a0, uint32_t a1,
                                         uint32_t a2, uint32_t a3,
                                         uint32_t b0, uint32_t b1) {
    asm volatile(
        "mma.sync.aligned.m16n8k8.row.col.f32.tf32.tf32.f32 "
        "{%0,%1,%2,%3}, {%4,%5,%6,%7}, {%8,%9}, {%0,%1,%2,%3};"
        : "+f"(c[0]), "+f"(c[1]), "+f"(c[2]), "+f"(c[3])
        : "r"(a0), "r"(a1), "r"(a2), "r"(a3), "r"(b0), "r"(b1));
}

__device__ __forceinline__ void red4(float* p, float4 v) {
    asm volatile("red.global.add.v4.f32 [%0], {%1,%2,%3,%4};"
                 :: "l"(p), "f"(v.x), "f"(v.y), "f"(v.z), "f"(v.w) : "memory");
}

// ------------------------------------------------------------------
__global__ void zero_kernel() {
    size_t i = (size_t)blockIdx.x * blockDim.x + threadIdx.x;
    size_t n_agg1 = (size_t)NN * RR * DIN / 4;
    size_t stride = (size_t)gridDim.x * blockDim.x;
    float4 z = make_float4(0.f, 0.f, 0.f, 0.f);
    for (size_t k = i; k < n_agg1; k += stride)
        reinterpret_cast<float4*>(g_agg1)[k] = z;
    for (size_t k = i; k < NR; k += stride)
        g_cnt[k] = 0;
}

__global__ void norm_kernel() {
    int i = blockIdx.x * blockDim.x + threadIdx.x;
    if (i < NR) {
        int c = g_cnt[i];
        g_norm[i] = c > 0 ? 1.0f / (float)c : 0.0f;
    }
}

// ------------------------------------------------------------------
// layer-1 scatter + degree count. One warp owns 32 edges (EE % 32 == 0):
// each lane loads one edge's (s,d,r) coalesced + counts it; then 16 iters,
// two half-warps process two edges per iter via shfl-broadcast indices.
__global__ void scatter1_kernel(const float* __restrict__ x,
                                const int* __restrict__ ei,
                                const int* __restrict__ et) {
    unsigned wid = (blockIdx.x * blockDim.x + threadIdx.x) >> 5;
    unsigned lane = threadIdx.x & 31;
    size_t e0 = (size_t)wid * 32;
    if (e0 >= EE) return;
    size_t my_e = e0 + lane;
    int s = ei[my_e];
    int d = ei[EE + my_e];
    int r = et[my_e];
    atomicAdd(&g_cnt[d * RR + r], 1);

    unsigned half = lane >> 4;   // 0 or 1
    unsigned hl = lane & 15;
#pragma unroll 4
    for (int j = 0; j < 32; j += 2) {
        int sl = j + half;
        int sj = __shfl_sync(0xffffffffu, s, sl);
        int dj = __shfl_sync(0xffffffffu, d, sl);
        int rj = __shfl_sync(0xffffffffu, r, sl);
        float4 v = *reinterpret_cast<const float4*>(x + (size_t)sj * DIN + hl * 4);
        red4(g_agg1 + ((size_t)dj * RR + rj) * DIN + hl * 4, v);
    }
}

// ------------------------------------------------------------------
// layer-1 transform (tf32): h = LN(leaky(Ahat @ [W1;root1] + bias1)); K=576
__global__ __launch_bounds__(256) void transform1_tc(
    const float* __restrict__ x, const float* __restrict__ W1,
    const float* __restrict__ root1, const float* __restrict__ bias1,
    const float* __restrict__ gamma1, const float* __restrict__ beta1) {
    __shared__ uint32_t As[128][36];
    __shared__ uint32_t Bs[32][136];
    int tid = threadIdx.x;
    int m0 = blockIdx.x * 128;
    int lane = tid & 31, warp = tid >> 5;
    int qr = lane >> 2, qc = lane & 3;

    float acc[16][4];
#pragma unroll
    for (int t = 0; t < 16; t++)
#pragma unroll
        for (int j = 0; j < 4; j++) acc[t][j] = 0.f;

    int arow = tid >> 1, akoff = (tid & 1) * 16;
    int brow = tid >> 3, bcoff = (tid & 7) * 16;

    for (int kk = 0; kk < 576; kk += 32) {
        {
            int n = m0 + arow;
            int kg = kk + akoff;
            float va[16];
            if (n < NN) {
                if (kg < 512) {
                    float nrm = g_norm[n * 8 + (kg >> 6)];
                    const float4* src =
                        reinterpret_cast<const float4*>(g_agg1 + (size_t)n * 512 + kg);
#pragma unroll
                    for (int i = 0; i < 4; i++) {
                        float4 v = src[i];
                        va[4*i+0] = v.x * nrm; va[4*i+1] = v.y * nrm;
                        va[4*i+2] = v.z * nrm; va[4*i+3] = v.w * nrm;
                    }
                } else {
                    const float4* src =
                        reinterpret_cast<const float4*>(x + (size_t)n * 64 + (kg - 512));
#pragma unroll
                    for (int i = 0; i < 4; i++) {
                        float4 v = src[i];
                        va[4*i+0] = v.x; va[4*i+1] = v.y;
                        va[4*i+2] = v.z; va[4*i+3] = v.w;
                    }
                }
            } else {
#pragma unroll
                for (int i = 0; i < 16; i++) va[i] = 0.f;
            }
#pragma unroll
            for (int i = 0; i < 16; i++) As[arow][akoff + i] = f2tf32(va[i]);
        }
        {
            int kg = kk + brow;
            const float* Brow = (kg < 512) ? (W1 + (size_t)kg * 128)
                                           : (root1 + (size_t)(kg - 512) * 128);
            const float4* src = reinterpret_cast<const float4*>(Brow + bcoff);
#pragma unroll
            for (int i = 0; i < 4; i++) {
                float4 v = src[i];
                Bs[brow][bcoff + 4*i + 0] = f2tf32(v.x);
                Bs[brow][bcoff + 4*i + 1] = f2tf32(v.y);
                Bs[brow][bcoff + 4*i + 2] = f2tf32(v.z);
                Bs[brow][bcoff + 4*i + 3] = f2tf32(v.w);
            }
        }
        __syncthreads();
#pragma unroll
        for (int k8 = 0; k8 < 4; k8++) {
            int k0 = k8 * 8;
            int ar = warp * 16 + qr;
            uint32_t a0 = As[ar][k0 + qc];
            uint32_t a1 = As[ar + 8][k0 + qc];
            uint32_t a2 = As[ar][k0 + qc + 4];
            uint32_t a3 = As[ar + 8][k0 + qc + 4];
#pragma unroll
            for (int t = 0; t < 16; t++) {
                uint32_t b0 = Bs[k0 + qc][t * 8 + qr];
                uint32_t b1 = Bs[k0 + qc + 4][t * 8 + qr];
                mma_tf32(acc[t], a0, a1, a2, a3, b0, b1);
            }
        }
        __syncthreads();
    }

    int r1 = m0 + warp * 16 + qr;
    int r2 = r1 + 8;
    float s1 = 0.f, q1 = 0.f, s2 = 0.f, q2 = 0.f;
#pragma unroll
    for (int t = 0; t < 16; t++) {
        int c = t * 8 + 2 * qc;
        float b0v = bias1[c], b1v = bias1[c + 1];
        float u;
        u = acc[t][0] + b0v; u = u >= 0.f ? u : 0.2f * u; acc[t][0] = u; s1 += u; q1 += u * u;
        u = acc[t][1] + b1v; u = u >= 0.f ? u : 0.2f * u; acc[t][1] = u; s1 += u; q1 += u * u;
        u = acc[t][2] + b0v; u = u >= 0.f ? u : 0.2f * u; acc[t][2] = u; s2 += u; q2 += u * u;
        u = acc[t][3] + b1v; u = u >= 0.f ? u : 0.2f * u; acc[t][3] = u; s2 += u; q2 += u * u;
    }
#pragma unroll
    for (int off = 1; off <= 2; off <<= 1) {
        s1 += __shfl_xor_sync(0xffffffffu, s1, off);
        q1 += __shfl_xor_sync(0xffffffffu, q1, off);
        s2 += __shfl_xor_sync(0xffffffffu, s2, off);
        q2 += __shfl_xor_sync(0xffffffffu, q2, off);
    }
    float mu1 = s1 * (1.f / 128.f), mu2 = s2 * (1.f / 128.f);
    float rs1 = rsqrtf(q1 * (1.f / 128.f) - mu1 * mu1 + LN_EPS);
    float rs2 = rsqrtf(q2 * (1.f / 128.f) - mu2 * mu2 + LN_EPS);
#pragma unroll
    for (int t = 0; t < 16; t++) {
        int c = t * 8 + 2 * qc;
        float g0 = gamma1[c], g1 = gamma1[c + 1];
        float e0 = beta1[c], e1 = beta1[c + 1];
        if (r1 < NN)
            *reinterpret_cast<float2*>(&g_h[(size_t)r1 * 128 + c]) =
                make_float2((acc[t][0] - mu1) * rs1 * g0 + e0,
                            (acc[t][1] - mu1) * rs1 * g1 + e1);
        if (r2 < NN)
            *reinterpret_cast<float2*>(&g_h[(size_t)r2 * 128 + c]) =
                make_float2((acc[t][2] - mu2) * rs2 * g0 + e0,
                            (acc[t][3] - mu2) * rs2 * g1 + e1);
    }
}

// ------------------------------------------------------------------
// layer-2 transform (tf32): grid.y = r in [0,9). r<8: hall[r] = h@W2_r.
// r==8: g_oagg = h@root2 (so scatter2 REDs on top, final is LN-only).
__global__ __launch_bounds__(256) void transform2_tc(const float* __restrict__ W2,
                                                     const float* __restrict__ root2) {
    __shared__ uint32_t As[128][36];
    __shared__ uint32_t Bs[32][72];
    int tid = threadIdx.x;
    int m0 = blockIdx.x * 128;
    int r = blockIdx.y;
    const float* Wr = (r < RR) ? (W2 + (size_t)r * 128 * 64) : root2;
    int lane = tid & 31, warp = tid >> 5;
    int qr = lane >> 2, qc = lane & 3;

    float acc[8][4];
#pragma unroll
    for (int t = 0; t < 8; t++)
#pragma unroll
        for (int j = 0; j < 4; j++) acc[t][j] = 0.f;

    int arow = tid >> 1, akoff = (tid & 1) * 16;
    int brow = tid >> 3, bcoff = (tid & 7) * 8;

    for (int kk = 0; kk < 128; kk += 32) {
        {
            int n = m0 + arow;
            if (n < NN) {
                const float4* src =
                    reinterpret_cast<const float4*>(g_h + (size_t)n * 128 + kk + akoff);
#pragma unroll
                for (int i = 0; i < 4; i++) {
                    float4 v = src[i];
                    As[arow][akoff + 4*i + 0] = f2tf32(v.x);
                    As[arow][akoff + 4*i + 1] = f2tf32(v.y);
                    As[arow][akoff + 4*i + 2] = f2tf32(v.z);
                    As[arow][akoff + 4*i + 3] = f2tf32(v.w);
                }
            } else {
#pragma unroll
                for (int i = 0; i < 16; i++) As[arow][akoff + i] = 0u;
            }
        }
        {
            const float4* src =
                reinterpret_cast<const float4*>(Wr + (size_t)(kk + brow) * 64 + bcoff);
#pragma unroll
            for (int i = 0; i < 2; i++) {
                float4 v = src[i];
                Bs[brow][bcoff + 4*i + 0] = f2tf32(v.x);
                Bs[brow][bcoff + 4*i + 1] = f2tf32(v.y);
                Bs[brow][bcoff + 4*i + 2] = f2tf32(v.z);
                Bs[brow][bcoff + 4*i + 3] = f2tf32(v.w);
            }
        }
        __syncthreads();
#pragma unroll
        for (int k8 = 0; k8 < 4; k8++) {
            int k0 = k8 * 8;
            int ar = warp * 16 + qr;
            uint32_t a0 = As[ar][k0 + qc];
            uint32_t a1 = As[ar + 8][k0 + qc];
            uint32_t a2 = As[ar][k0 + qc + 4];
            uint32_t a3 = As[ar + 8][k0 + qc + 4];
#pragma unroll
            for (int t = 0; t < 8; t++) {
                uint32_t b0 = Bs[k0 + qc][t * 8 + qr];
                uint32_t b1 = Bs[k0 + qc + 4][t * 8 + qr];
                mma_tf32(acc[t], a0, a1, a2, a3, b0, b1);
            }
        }
        __syncthreads();
    }
    int r1 = m0 + warp * 16 + qr;
    int r2 = r1 + 8;
    float* dst = (r < RR) ? (g_hall + (size_t)r * NN * 64) : g_oagg;
#pragma unroll
    for (int t = 0; t < 8; t++) {
        int c = t * 8 + 2 * qc;
        if (r1 < NN)
            *reinterpret_cast<float2*>(dst + (size_t)r1 * 64 + c) =
                make_float2(acc[t][0], acc[t][1]);
        if (r2 < NN)
            *reinterpret_cast<float2*>(dst + (size_t)r2 * 64 + c) =
                make_float2(acc[t][2], acc[t][3]);
    }
}

// ------------------------------------------------------------------
// layer-2 scatter (warp-cooperative): oagg[dst,:] += norm * hall[rel,src,:]
__global__ void scatter2_kernel(const int* __restrict__ ei,
                                const int* __restrict__ et) {
    unsigned wid = (blockIdx.x * blockDim.x + threadIdx.x) >> 5;
    unsigned lane = threadIdx.x & 31;
    size_t e0 = (size_t)wid * 32;
    if (e0 >= EE) return;
    size_t my_e = e0 + lane;
    int s = ei[my_e];
    int d = ei[EE + my_e];
    int r = et[my_e];
    float nrm = g_norm[d * RR + r];

    unsigned half = lane >> 4;
    unsigned hl = lane & 15;
#pragma unroll 4
    for (int j = 0; j < 32; j += 2) {
        int sl = j + half;
        int sj = __shfl_sync(0xffffffffu, s, sl);
        int dj = __shfl_sync(0xffffffffu, d, sl);
        int rj = __shfl_sync(0xffffffffu, r, sl);
        float nj = __shfl_sync(0xffffffffu, nrm, sl);
        float4 v = *reinterpret_cast<const float4*>(
            g_hall + ((size_t)rj * NN + sj) * 64 + hl * 4);
        v.x *= nj; v.y *= nj; v.z *= nj; v.w *= nj;
        red4(g_oagg + (size_t)dj * 64 + hl * 4, v);
    }
}

// ------------------------------------------------------------------
// final: out = LN(oagg + bias2) — oagg already holds h@root2 + msg sum.
// 16 lanes per node, float4 per lane.
__global__ void final_ln(const float* __restrict__ bias2,
                         const float* __restrict__ gamma2,
                         const float* __restrict__ beta2,
                         float* __restrict__ out) {
    int t = blockIdx.x * blockDim.x + threadIdx.x;
    int n = t >> 4, hl = t & 15;
    if (n >= NN) return;
    float4 v = *reinterpret_cast<const float4*>(g_oagg + (size_t)n * 64 + hl * 4);
    float4 b = *reinterpret_cast<const float4*>(bias2 + hl * 4);
    v.x += b.x; v.y += b.y; v.z += b.z; v.w += b.w;
    float s = v.x + v.y + v.z + v.w;
    float q = v.x * v.x + v.y * v.y + v.z * v.z + v.w * v.w;
#pragma unroll
    for (int off = 8; off; off >>= 1) {
        s += __shfl_xor_sync(0xffffffffu, s, off);
        q += __shfl_xor_sync(0xffffffffu, q, off);
    }
    float mu = s * (1.f / 64.f);
    float rstd = rsqrtf(q * (1.f / 64.f) - mu * mu + LN_EPS);
    float4 g = *reinterpret_cast<const float4*>(gamma2 + hl * 4);
    float4 e = *reinterpret_cast<const float4*>(beta2 + hl * 4);
    float4 o;
    o.x = (v.x - mu) * rstd * g.x + e.x;
    o.y = (v.y - mu) * rstd * g.y + e.y;
    o.z = (v.z - mu) * rstd * g.z + e.z;
    o.w = (v.w - mu) * rstd * g.w + e.w;
    *reinterpret_cast<float4*>(out + (size_t)n * 64 + hl * 4) = o;
}

// ------------------------------------------------------------------
extern "C" void kernel_launch(void* const* d_in, const int* in_sizes, int n_in,
                              void* d_out, int out_size) {
    const float* x      = (const float*)d_in[0];
    const int*   ei     = (const int*)d_in[1];
    const int*   et     = (const int*)d_in[2];
    const float* W1     = (const float*)d_in[3];
    const float* root1  = (const float*)d_in[4];
    const float* bias1  = (const float*)d_in[5];
    const float* gamma1 = (const float*)d_in[6];
    const float* beta1  = (const float*)d_in[7];
    const float* W2     = (const float*)d_in[8];
    const float* root2  = (const float*)d_in[9];
    const float* bias2  = (const float*)d_in[10];
    const float* gamma2 = (const float*)d_in[11];
    const float* beta2  = (const float*)d_in[12];
    float*       out    = (float*)d_out;

    zero_kernel<<<1024, 256>>>();
    scatter1_kernel<<<(EE + 255) / 256, 256>>>(x, ei, et);   // 1 warp = 32 edges
    norm_kernel<<<(NR + 255) / 256, 256>>>();
    int mblocks = (NN + 127) / 128;
    transform1_tc<<<mblocks, 256>>>(x, W1, root1, bias1, gamma1, beta1);
    dim3 g2(mblocks, RR + 1);   // 8 relations + root2 -> g_oagg
    transform2_tc<<<g2, 256>>>(W2, root2);
    scatter2_kernel<<<(EE + 255) / 256, 256>>>(ei, et);
    final_ln<<<(NN * 16 + 255) / 256, 256>>>(bias2, gamma2, beta2, out);
}

// round 7
// speedup vs baseline: 2.3867x; 1.0284x over previous
#include <cuda_runtime.h>
#include <cstdint>

#define NN 50000
#define EE 800000
#define RR 8
#define DIN 64
#define DHID 128
#define DOUT 64
#define NR (NN*RR)
#define LN_EPS 1e-5f

// ---- scratch (device globals; no runtime allocation); 16B-aligned ----
__device__ __align__(16) float g_agg1[(size_t)NN*RR*DIN]; // per-(node,rel) sum of x[src]
__device__ __align__(16) float g_norm[NR];                // 1/cnt per (node,rel)
__device__ __align__(16) int   g_cnt[NR];
__device__ __align__(16) float g_h[(size_t)NN*DHID];      // layer-1 output (post LN)
__device__ __align__(16) float g_hall[(size_t)RR*NN*DOUT];// h @ W2_r per relation
__device__ __align__(16) float g_oagg[(size_t)NN*DOUT];   // h@root2 + normalized msg sum

__device__ __forceinline__ uint32_t f2tf32(float f) {
    uint32_t v;
    asm("cvt.rna.tf32.f32 %0, %1;" : "=r"(v) : "f"(f));
    return v;
}

__device__ __forceinline__ void mma_tf32(float* c, uint32_t a0, uint32_t a1,
                                         uint32_t a2, uint32_t a3,
                                         uint32_t b0, uint32_t b1) {
    asm volatile(
        "mma.sync.aligned.m16n8k8.row.col.f32.tf32.tf32.f32 "
        "{%0,%1,%2,%3}, {%4,%5,%6,%7}, {%8,%9}, {%0,%1,%2,%3};"
        : "+f"(c[0]), "+f"(c[1]), "+f"(c[2]), "+f"(c[3])
        : "r"(a0), "r"(a1), "r"(a2), "r"(a3), "r"(b0), "r"(b1));
}

__device__ __forceinline__ void red4(float* p, float4 v) {
    asm volatile("red.global.add.v4.f32 [%0], {%1,%2,%3,%4};"
                 :: "l"(p), "f"(v.x), "f"(v.y), "f"(v.z), "f"(v.w) : "memory");
}

// ------------------------------------------------------------------
__global__ void zero_kernel() {
    size_t i = (size_t)blockIdx.x * blockDim.x + threadIdx.x;
    size_t n_agg1 = (size_t)NN * RR * DIN / 4;
    size_t stride = (size_t)gridDim.x * blockDim.x;
    float4 z = make_float4(0.f, 0.f, 0.f, 0.f);
    for (size_t k = i; k < n_agg1; k += stride)
        reinterpret_cast<float4*>(g_agg1)[k] = z;
    for (size_t k = i; k < NR; k += stride)
        g_cnt[k] = 0;
}

__global__ void norm_kernel() {
    int i = blockIdx.x * blockDim.x + threadIdx.x;
    if (i < NR) {
        int c = g_cnt[i];
        g_norm[i] = c > 0 ? 1.0f / (float)c : 0.0f;
    }
}

// ------------------------------------------------------------------
// layer-1 scatter + degree count. One warp owns 32 edges.
__global__ void scatter1_kernel(const float* __restrict__ x,
                                const int* __restrict__ ei,
                                const int* __restrict__ et) {
    unsigned wid = (blockIdx.x * blockDim.x + threadIdx.x) >> 5;
    unsigned lane = threadIdx.x & 31;
    size_t e0 = (size_t)wid * 32;
    if (e0 >= EE) return;
    size_t my_e = e0 + lane;
    int s = ei[my_e];
    int d = ei[EE + my_e];
    int r = et[my_e];
    atomicAdd(&g_cnt[d * RR + r], 1);

    unsigned half = lane >> 4;
    unsigned hl = lane & 15;
#pragma unroll 4
    for (int j = 0; j < 32; j += 2) {
        int sl = j + half;
        int sj = __shfl_sync(0xffffffffu, s, sl);
        int dj = __shfl_sync(0xffffffffu, d, sl);
        int rj = __shfl_sync(0xffffffffu, r, sl);
        float4 v = *reinterpret_cast<const float4*>(x + (size_t)sj * DIN + hl * 4);
        red4(g_agg1 + ((size_t)dj * RR + rj) * DIN + hl * 4, v);
    }
}

// ------------------------------------------------------------------
// layer-1 transform (tf32): h = LN(leaky(Ahat @ [W1;root1] + bias1)); K=576
// 8 warps as 4(M) x 2(N); warp tile 32x64 -> 1.5 LDS per MMA.
__global__ __launch_bounds__(256) void transform1_tc(
    const float* __restrict__ x, const float* __restrict__ W1,
    const float* __restrict__ root1, const float* __restrict__ bias1,
    const float* __restrict__ gamma1, const float* __restrict__ beta1) {
    __shared__ uint32_t As[128][36];
    __shared__ uint32_t Bs[32][136];
    __shared__ float red_s[128][2];
    __shared__ float red_q[128][2];
    int tid = threadIdx.x;
    int m0 = blockIdx.x * 128;
    int lane = tid & 31, warp = tid >> 5;
    int warp_m = warp >> 1, warp_n = warp & 1;
    int qr = lane >> 2, qc = lane & 3;

    float acc[2][8][4];
#pragma unroll
    for (int mt = 0; mt < 2; mt++)
#pragma unroll
        for (int t = 0; t < 8; t++)
#pragma unroll
            for (int j = 0; j < 4; j++) acc[mt][t][j] = 0.f;

    int arow = tid >> 1, akoff = (tid & 1) * 16;
    int brow = tid >> 3, bcoff = (tid & 7) * 16;

    for (int kk = 0; kk < 576; kk += 32) {
        {
            int n = m0 + arow;
            int kg = kk + akoff;
            float va[16];
            if (n < NN) {
                if (kg < 512) {
                    float nrm = g_norm[n * 8 + (kg >> 6)];
                    const float4* src =
                        reinterpret_cast<const float4*>(g_agg1 + (size_t)n * 512 + kg);
#pragma unroll
                    for (int i = 0; i < 4; i++) {
                        float4 v = src[i];
                        va[4*i+0] = v.x * nrm; va[4*i+1] = v.y * nrm;
                        va[4*i+2] = v.z * nrm; va[4*i+3] = v.w * nrm;
                    }
                } else {
                    const float4* src =
                        reinterpret_cast<const float4*>(x + (size_t)n * 64 + (kg - 512));
#pragma unroll
                    for (int i = 0; i < 4; i++) {
                        float4 v = src[i];
                        va[4*i+0] = v.x; va[4*i+1] = v.y;
                        va[4*i+2] = v.z; va[4*i+3] = v.w;
                    }
                }
            } else {
#pragma unroll
                for (int i = 0; i < 16; i++) va[i] = 0.f;
            }
#pragma unroll
            for (int i = 0; i < 16; i++) As[arow][akoff + i] = f2tf32(va[i]);
        }
        {
            int kg = kk + brow;
            const float* Brow = (kg < 512) ? (W1 + (size_t)kg * 128)
                                           : (root1 + (size_t)(kg - 512) * 128);
            const float4* src = reinterpret_cast<const float4*>(Brow + bcoff);
#pragma unroll
            for (int i = 0; i < 4; i++) {
                float4 v = src[i];
                Bs[brow][bcoff + 4*i + 0] = f2tf32(v.x);
                Bs[brow][bcoff + 4*i + 1] = f2tf32(v.y);
                Bs[brow][bcoff + 4*i + 2] = f2tf32(v.z);
                Bs[brow][bcoff + 4*i + 3] = f2tf32(v.w);
            }
        }
        __syncthreads();
#pragma unroll
        for (int k8 = 0; k8 < 4; k8++) {
            int k0 = k8 * 8;
            uint32_t a[2][4];
#pragma unroll
            for (int mt = 0; mt < 2; mt++) {
                int ar = warp_m * 32 + mt * 16 + qr;
                a[mt][0] = As[ar][k0 + qc];
                a[mt][1] = As[ar + 8][k0 + qc];
                a[mt][2] = As[ar][k0 + qc + 4];
                a[mt][3] = As[ar + 8][k0 + qc + 4];
            }
#pragma unroll
            for (int t = 0; t < 8; t++) {
                int cn = warp_n * 64 + t * 8 + qr;
                uint32_t b0 = Bs[k0 + qc][cn];
                uint32_t b1 = Bs[k0 + qc + 4][cn];
                mma_tf32(acc[0][t], a[0][0], a[0][1], a[0][2], a[0][3], b0, b1);
                mma_tf32(acc[1][t], a[1][0], a[1][1], a[1][2], a[1][3], b0, b1);
            }
        }
        __syncthreads();
    }

    // ---- epilogue: bias + LeakyReLU; partial row sums -> smem; LN(128) ----
#pragma unroll
    for (int mt = 0; mt < 2; mt++) {
        float s[2] = {0.f, 0.f}, q[2] = {0.f, 0.f};
#pragma unroll
        for (int t = 0; t < 8; t++) {
            int c = warp_n * 64 + t * 8 + 2 * qc;
            float b0v = bias1[c], b1v = bias1[c + 1];
            float u;
            u = acc[mt][t][0] + b0v; u = u >= 0.f ? u : 0.2f * u; acc[mt][t][0] = u; s[0] += u; q[0] += u * u;
            u = acc[mt][t][1] + b1v; u = u >= 0.f ? u : 0.2f * u; acc[mt][t][1] = u; s[0] += u; q[0] += u * u;
            u = acc[mt][t][2] + b0v; u = u >= 0.f ? u : 0.2f * u; acc[mt][t][2] = u; s[1] += u; q[1] += u * u;
            u = acc[mt][t][3] + b1v; u = u >= 0.f ? u : 0.2f * u; acc[mt][t][3] = u; s[1] += u; q[1] += u * u;
        }
#pragma unroll
        for (int off = 1; off <= 2; off <<= 1) {
            s[0] += __shfl_xor_sync(0xffffffffu, s[0], off);
            q[0] += __shfl_xor_sync(0xffffffffu, q[0], off);
            s[1] += __shfl_xor_sync(0xffffffffu, s[1], off);
            q[1] += __shfl_xor_sync(0xffffffffu, q[1], off);
        }
        if (qc == 0) {
            int lr = warp_m * 32 + mt * 16 + qr;
            red_s[lr][warp_n] = s[0]; red_q[lr][warp_n] = q[0];
            red_s[lr + 8][warp_n] = s[1]; red_q[lr + 8][warp_n] = q[1];
        }
    }
    __syncthreads();
#pragma unroll
    for (int mt = 0; mt < 2; mt++) {
#pragma unroll
        for (int h = 0; h < 2; h++) {
            int lr = warp_m * 32 + mt * 16 + qr + 8 * h;
            int gm = m0 + lr;
            float S = red_s[lr][0] + red_s[lr][1];
            float Q = red_q[lr][0] + red_q[lr][1];
            float mu = S * (1.f / 128.f);
            float rstd = rsqrtf(Q * (1.f / 128.f) - mu * mu + LN_EPS);
            if (gm < NN) {
#pragma unroll
                for (int t = 0; t < 8; t++) {
                    int c = warp_n * 64 + t * 8 + 2 * qc;
                    float g0 = gamma1[c], g1 = gamma1[c + 1];
                    float e0 = beta1[c], e1 = beta1[c + 1];
                    *reinterpret_cast<float2*>(&g_h[(size_t)gm * 128 + c]) =
                        make_float2((acc[mt][t][2*h] - mu) * rstd * g0 + e0,
                                    (acc[mt][t][2*h+1] - mu) * rstd * g1 + e1);
                }
            }
        }
    }
}

// ------------------------------------------------------------------
// layer-2 transform (tf32): grid.y = r in [0,9). r<8: hall[r]=h@W2_r; r==8:
// g_oagg = h@root2. 128 threads, 4 warps, warp tile 32x64 over BM=128.
__global__ __launch_bounds__(128) void transform2_tc(const float* __restrict__ W2,
                                                     const float* __restrict__ root2) {
    __shared__ uint32_t As[128][36];
    __shared__ uint32_t Bs[32][72];
    int tid = threadIdx.x;
    int m0 = blockIdx.x * 128;
    int r = blockIdx.y;
    const float* Wr = (r < RR) ? (W2 + (size_t)r * 128 * 64) : root2;
    int lane = tid & 31, warp_m = tid >> 5;
    int qr = lane >> 2, qc = lane & 3;

    float acc[2][8][4];
#pragma unroll
    for (int mt = 0; mt < 2; mt++)
#pragma unroll
        for (int t = 0; t < 8; t++)
#pragma unroll
            for (int j = 0; j < 4; j++) acc[mt][t][j] = 0.f;

    int arow = tid >> 1, akoff = (tid & 1) * 16;   // + 64-row second pass
    int brow = tid >> 2, bcoff = (tid & 3) * 16;

    for (int kk = 0; kk < 128; kk += 32) {
#pragma unroll
        for (int rr = 0; rr < 2; rr++) {
            int lr = rr * 64 + arow;
            int n = m0 + lr;
            if (n < NN) {
                const float4* src =
                    reinterpret_cast<const float4*>(g_h + (size_t)n * 128 + kk + akoff);
#pragma unroll
                for (int i = 0; i < 4; i++) {
                    float4 v = src[i];
                    As[lr][akoff + 4*i + 0] = f2tf32(v.x);
                    As[lr][akoff + 4*i + 1] = f2tf32(v.y);
                    As[lr][akoff + 4*i + 2] = f2tf32(v.z);
                    As[lr][akoff + 4*i + 3] = f2tf32(v.w);
                }
            } else {
#pragma unroll
                for (int i = 0; i < 16; i++) As[lr][akoff + i] = 0u;
            }
        }
        {
            const float4* src =
                reinterpret_cast<const float4*>(Wr + (size_t)(kk + brow) * 64 + bcoff);
#pragma unroll
            for (int i = 0; i < 4; i++) {
                float4 v = src[i];
                Bs[brow][bcoff + 4*i + 0] = f2tf32(v.x);
                Bs[brow][bcoff + 4*i + 1] = f2tf32(v.y);
                Bs[brow][bcoff + 4*i + 2] = f2tf32(v.z);
                Bs[brow][bcoff + 4*i + 3] = f2tf32(v.w);
            }
        }
        __syncthreads();
#pragma unroll
        for (int k8 = 0; k8 < 4; k8++) {
            int k0 = k8 * 8;
            uint32_t a[2][4];
#pragma unroll
            for (int mt = 0; mt < 2; mt++) {
                int ar = warp_m * 32 + mt * 16 + qr;
                a[mt][0] = As[ar][k0 + qc];
                a[mt][1] = As[ar + 8][k0 + qc];
                a[mt][2] = As[ar][k0 + qc + 4];
                a[mt][3] = As[ar + 8][k0 + qc + 4];
            }
#pragma unroll
            for (int t = 0; t < 8; t++) {
                int cn = t * 8 + qr;
                uint32_t b0 = Bs[k0 + qc][cn];
                uint32_t b1 = Bs[k0 + qc + 4][cn];
                mma_tf32(acc[0][t], a[0][0], a[0][1], a[0][2], a[0][3], b0, b1);
                mma_tf32(acc[1][t], a[1][0], a[1][1], a[1][2], a[1][3], b0, b1);
            }
        }
        __syncthreads();
    }
    float* dst = (r < RR) ? (g_hall + (size_t)r * NN * 64) : g_oagg;
#pragma unroll
    for (int mt = 0; mt < 2; mt++) {
        int r1 = m0 + warp_m * 32 + mt * 16 + qr;
        int r2 = r1 + 8;
#pragma unroll
        for (int t = 0; t < 8; t++) {
            int c = t * 8 + 2 * qc;
            if (r1 < NN)
                *reinterpret_cast<float2*>(dst + (size_t)r1 * 64 + c) =
                    make_float2(acc[mt][t][0], acc[mt][t][1]);
            if (r2 < NN)
                *reinterpret_cast<float2*>(dst + (size_t)r2 * 64 + c) =
                    make_float2(acc[mt][t][2], acc[mt][t][3]);
        }
    }
}

// ------------------------------------------------------------------
// layer-2 scatter (warp-cooperative): oagg[dst,:] += norm * hall[rel,src,:]
__global__ void scatter2_kernel(const int* __restrict__ ei,
                                const int* __restrict__ et) {
    unsigned wid = (blockIdx.x * blockDim.x + threadIdx.x) >> 5;
    unsigned lane = threadIdx.x & 31;
    size_t e0 = (size_t)wid * 32;
    if (e0 >= EE) return;
    size_t my_e = e0 + lane;
    int s = ei[my_e];
    int d = ei[EE + my_e];
    int r = et[my_e];
    float nrm = g_norm[d * RR + r];

    unsigned half = lane >> 4;
    unsigned hl = lane & 15;
#pragma unroll 4
    for (int j = 0; j < 32; j += 2) {
        int sl = j + half;
        int sj = __shfl_sync(0xffffffffu, s, sl);
        int dj = __shfl_sync(0xffffffffu, d, sl);
        int rj = __shfl_sync(0xffffffffu, r, sl);
        float nj = __shfl_sync(0xffffffffu, nrm, sl);
        float4 v = *reinterpret_cast<const float4*>(
            g_hall + ((size_t)rj * NN + sj) * 64 + hl * 4);
        v.x *= nj; v.y *= nj; v.z *= nj; v.w *= nj;
        red4(g_oagg + (size_t)dj * 64 + hl * 4, v);
    }
}

// ------------------------------------------------------------------
// final: out = LN(oagg + bias2)
__global__ void final_ln(const float* __restrict__ bias2,
                         const float* __restrict__ gamma2,
                         const float* __restrict__ beta2,
                         float* __restrict__ out) {
    int t = blockIdx.x * blockDim.x + threadIdx.x;
    int n = t >> 4, hl = t & 15;
    if (n >= NN) return;
    float4 v = *reinterpret_cast<const float4*>(g_oagg + (size_t)n * 64 + hl * 4);
    float4 b = *reinterpret_cast<const float4*>(bias2 + hl * 4);
    v.x += b.x; v.y += b.y; v.z += b.z; v.w += b.w;
    float s = v.x + v.y + v.z + v.w;
    float q = v.x * v.x + v.y * v.y + v.z * v.z + v.w * v.w;
#pragma unroll
    for (int off = 8; off; off >>= 1) {
        s += __shfl_xor_sync(0xffffffffu, s, off);
        q += __shfl_xor_sync(0xffffffffu, q, off);
    }
    float mu = s * (1.f / 64.f);
    float rstd = rsqrtf(q * (1.f / 64.f) - mu * mu + LN_EPS);
    float4 g = *reinterpret_cast<const float4*>(gamma2 + hl * 4);
    float4 e = *reinterpret_cast<const float4*>(beta2 + hl * 4);
    float4 o;
    o.x = (v.x - mu) * rstd * g.x + e.x;
    o.y = (v.y - mu) * rstd * g.y + e.y;
    o.z = (v.z - mu) * rstd * g.z + e.z;
    o.w = (v.w - mu) * rstd * g.w + e.w;
    *reinterpret_cast<float4*>(out + (size_t)n * 64 + hl * 4) = o;
}

// ------------------------------------------------------------------
extern "C" void kernel_launch(void* const* d_in, const int* in_sizes, int n_in,
                              void* d_out, int out_size) {
    const float* x      = (const float*)d_in[0];
    const int*   ei     = (const int*)d_in[1];
    const int*   et     = (const int*)d_in[2];
    const float* W1     = (const float*)d_in[3];
    const float* root1  = (const float*)d_in[4];
    const float* bias1  = (const float*)d_in[5];
    const float* gamma1 = (const float*)d_in[6];
    const float* beta1  = (const float*)d_in[7];
    const float* W2     = (const float*)d_in[8];
    const float* root2  = (const float*)d_in[9];
    const float* bias2  = (const float*)d_in[10];
    const float* gamma2 = (const float*)d_in[11];
    const float* beta2  = (const float*)d_in[12];
    float*       out    = (float*)d_out;

    zero_kernel<<<1024, 256>>>();
    scatter1_kernel<<<(EE + 255) / 256, 256>>>(x, ei, et);
    norm_kernel<<<(NR + 255) / 256, 256>>>();
    int mblocks = (NN + 127) / 128;
    transform1_tc<<<mblocks, 256>>>(x, W1, root1, bias1, gamma1, beta1);
    dim3 g2(mblocks, RR + 1);
    transform2_tc<<<g2, 128>>>(W2, root2);
    scatter2_kernel<<<(EE + 255) / 256, 256>>>(ei, et);
    final_ln<<<(NN * 16 + 255) / 256, 256>>>(bias2, gamma2, beta2, out);
}